// round 7
// baseline (speedup 1.0000x reference)
#include <cuda_runtime.h>

// Sobel edge magnitude + channel mean.
// x: [B=16, C=64, H=256, W=256] f32 -> out: [B,1,H,W] f32
//
// Separable: p_i = x[i][w+1]-x[i][w-1], q_i = x[i][w-1]+2x[i][w]+x[i][w+1]
//   gx(r) = p_r + 2 p_{r+1} + p_{r+2},   gy(r) = q_{r+2} - q_r
//
// R7 changes vs R6:
//  - 4-channel interleave (c, c+8, c+16, c+24 per k-iter): 12 independent
//    LDGs per row step. __launch_bounds__(256,2) -> ~128-reg budget.
//  - Rows loaded as ulonglong2 so packed pairs (v0,v1),(v2,v3) come straight
//    from the load regs; only 3 mov.b64 packs per row/channel remain.

#define BB 16
#define CC 64
#define HH 256
#define WW 256
#define RR 4          // output rows per tile
#define NWARPS 8      // warps per block (channel stride)
#define NCH 4         // channels interleaved per k-iteration
#define TW 128        // columns per warp tile (32 lanes * 4)
#define HSTRIPS (HH / RR)

typedef unsigned long long u64;

__device__ __forceinline__ float sqrt_approx(float v) {
    float y;
    asm("sqrt.approx.f32 %0, %1;" : "=f"(y) : "f"(v));
    return y;
}
__device__ __forceinline__ u64 pk(float lo, float hi) {
    u64 r; asm("mov.b64 %0, {%1, %2};" : "=l"(r) : "f"(lo), "f"(hi)); return r;
}
__device__ __forceinline__ void upk(float& lo, float& hi, u64 v) {
    asm("mov.b64 {%0, %1}, %2;" : "=f"(lo), "=f"(hi) : "l"(v));
}
__device__ __forceinline__ u64 add2(u64 a, u64 b) {
    u64 r; asm("add.rn.f32x2 %0, %1, %2;" : "=l"(r) : "l"(a), "l"(b)); return r;
}
__device__ __forceinline__ u64 fma2(u64 a, u64 b, u64 c) {
    u64 r; asm("fma.rn.f32x2 %0, %1, %2, %3;" : "=l"(r) : "l"(a), "l"(b), "l"(c)); return r;
}

__global__ __launch_bounds__(256, 2)
void sobel_mean_kernel(const float* __restrict__ x, float* __restrict__ out) {
    const int wq   = blockIdx.x;   // column tile: 0..1
    const int hs   = blockIdx.y;   // row strip:   0..63
    const int b    = blockIdx.z;
    const int tid  = threadIdx.x;
    const int wid  = tid >> 5;
    const int lane = tid & 31;

    const int gw4 = wq * TW + lane * 4;  // first of this lane's 4 columns
    const int gh0 = hs * RR;             // first output row of the strip

    const bool top_oob = (hs == 0);
    const bool bot_oob = (hs == HSTRIPS - 1);

    __shared__ float s_acc[NWARPS][RR * TW];   // 16 KB

    const u64 TWO2 = pk(2.0f, 2.0f);
    const u64 NEG1 = pk(-1.0f, -1.0f);
    const u64 EPS2 = pk(1e-12f, 1e-12f);

    float4 acc[RR];
#pragma unroll
    for (int r = 0; r < RR; r++) acc[r] = make_float4(0.f, 0.f, 0.f, 0.f);

    const bool has_left  = (gw4 != 0);
    const bool has_right = (gw4 + 4 != WW);

#pragma unroll 1
    for (int k = 0; k < CC / NWARPS; k += NCH) {
        const float* __restrict__ plane[NCH];
        plane[0] = x + ((size_t)(b * CC + wid + NWARPS * k)) * (HH * WW);
#pragma unroll
        for (int j = 1; j < NCH; j++)
            plane[j] = plane[j - 1] + (size_t)NWARPS * (HH * WW);

        // Rolling packed rows i-2, i-1 per channel
        u64 p0l[NCH], p0h[NCH], p1l[NCH], p1h[NCH];
        u64 q0l[NCH], q0h[NCH], q1l[NCH], q1h[NCH];
#pragma unroll
        for (int j = 0; j < NCH; j++) {
            p0l[j] = p0h[j] = p1l[j] = p1h[j] = 0;
            q0l[j] = q0h[j] = q1l[j] = q1h[j] = 0;
        }

#pragma unroll
        for (int i = 0; i < RR + 2; i++) {
            const int gh = gh0 - 1 + i;
            const bool oob = (i == 0 && top_oob) || (i == RR + 1 && bot_oob);

            // ---- issue all loads up front (NCH planes) ----
            ulonglong2 vv[NCH];
            float lft[NCH], rgt[NCH];
#pragma unroll
            for (int j = 0; j < NCH; j++) {
                const float* __restrict__ row = plane[j] + gh * WW;
                if (oob) {
                    vv[j].x = 0; vv[j].y = 0;
                    lft[j] = 0.f; rgt[j] = 0.f;
                } else {
                    vv[j]  = *reinterpret_cast<const ulonglong2*>(row + gw4);
                    lft[j] = has_left  ? row[gw4 - 1] : 0.f;
                    rgt[j] = has_right ? row[gw4 + 4] : 0.f;
                }
            }

            // ---- p/q for all channels ----
            u64 pl[NCH], ph[NCH], ql[NCH], qh[NCH];
#pragma unroll
            for (int j = 0; j < NCH; j++) {
                const u64 cl = vv[j].x;            // (v0, v1)
                const u64 ch = vv[j].y;            // (v2, v3)
                float v0, v1, v2, v3;
                upk(v0, v1, cl);
                upk(v2, v3, ch);
                const u64 ll = pk(lft[j], v0);
                const u64 lh = pk(v1, v2);
                const u64 rh = pk(v3, rgt[j]);
                pl[j] = fma2(NEG1, ll, lh);
                ph[j] = fma2(NEG1, lh, rh);
                ql[j] = add2(fma2(cl, TWO2, ll), lh);
                qh[j] = add2(fma2(ch, TWO2, lh), rh);
            }

            if (i >= 2) {
                const int r = i - 2;
                float s0 = 0.f, s1 = 0.f, s2 = 0.f, s3 = 0.f;
#pragma unroll
                for (int j = 0; j < NCH; j++) {
                    const u64 gxl = add2(fma2(p1l[j], TWO2, p0l[j]), pl[j]);
                    const u64 gxh = add2(fma2(p1h[j], TWO2, p0h[j]), ph[j]);
                    const u64 gyl = fma2(NEG1, q0l[j], ql[j]);
                    const u64 gyh = fma2(NEG1, q0h[j], qh[j]);
                    const u64 m_l = fma2(gxl, gxl, fma2(gyl, gyl, EPS2));
                    const u64 m_h = fma2(gxh, gxh, fma2(gyh, gyh, EPS2));
                    float m0, m1, m2, m3;
                    upk(m0, m1, m_l);
                    upk(m2, m3, m_h);
                    s0 += sqrt_approx(m0);
                    s1 += sqrt_approx(m1);
                    s2 += sqrt_approx(m2);
                    s3 += sqrt_approx(m3);
                }
                acc[r].x += s0; acc[r].y += s1;
                acc[r].z += s2; acc[r].w += s3;
            }
#pragma unroll
            for (int j = 0; j < NCH; j++) {
                p0l[j] = p1l[j]; p0h[j] = p1h[j]; p1l[j] = pl[j]; p1h[j] = ph[j];
                q0l[j] = q1l[j]; q0h[j] = q1h[j]; q1l[j] = ql[j]; q1h[j] = qh[j];
            }
        }
    }

    // Stage per-warp partials, then block-reduce across the 8 warps.
#pragma unroll
    for (int r = 0; r < RR; r++)
        *reinterpret_cast<float4*>(&s_acc[wid][r * TW + lane * 4]) = acc[r];
    __syncthreads();

    const float inv = 1.0f / (float)CC;
#pragma unroll
    for (int j = 0; j < (RR * TW) / 256; j++) {
        const int px = tid + 256 * j;          // 0..511
        float s = 0.f;
#pragma unroll
        for (int w = 0; w < NWARPS; w++) s += s_acc[w][px];
        const int r   = px / TW;
        const int col = px % TW;
        out[((size_t)b * HH + (gh0 + r)) * WW + wq * TW + col] = s * inv;
    }
}

extern "C" void kernel_launch(void* const* d_in, const int* in_sizes, int n_in,
                              void* d_out, int out_size) {
    const float* x = (const float*)d_in[0];
    float* out = (float*)d_out;
    dim3 grid(WW / TW, HSTRIPS, BB);   // (2, 64, 16) = 2048 blocks
    sobel_mean_kernel<<<grid, 256>>>(x, out);
}

// round 8
// speedup vs baseline: 1.4184x; 1.4184x over previous
#include <cuda_runtime.h>

// Sobel edge magnitude + channel mean.
// x: [B=16, C=64, H=256, W=256] f32 -> out: [B,1,H,W] f32
//
// Separable: p_i = x[i][w+1]-x[i][w-1], q_i = x[i][w-1]+2x[i][w]+x[i][w+1]
//   gx(r) = p_r + 2 p_{r+1} + p_{r+2},   gy(r) = q_{r+2} - q_r
//
// R8 changes vs R6/R7:
//  - Back to 1 channel per k-iteration, but ALL 6 rows of the strip are
//    loaded up front (18 independent LDGs, ~3KB in flight per warp) before
//    the rolling p/q window consumes them. Max MLP within the 84-reg /
//    3-CTA budget; R7 showed widening channels past the RF ceiling loses.

#define BB 16
#define CC 64
#define HH 256
#define WW 256
#define RR 4          // output rows per tile
#define NROWS (RR + 2)
#define NWARPS 8      // warps per block (channel stride)
#define TW 128        // columns per warp tile (32 lanes * 4)
#define HSTRIPS (HH / RR)

typedef unsigned long long u64;

__device__ __forceinline__ float sqrt_approx(float v) {
    float y;
    asm("sqrt.approx.f32 %0, %1;" : "=f"(y) : "f"(v));
    return y;
}
__device__ __forceinline__ u64 pk(float lo, float hi) {
    u64 r; asm("mov.b64 %0, {%1, %2};" : "=l"(r) : "f"(lo), "f"(hi)); return r;
}
__device__ __forceinline__ void upk(float& lo, float& hi, u64 v) {
    asm("mov.b64 {%0, %1}, %2;" : "=f"(lo), "=f"(hi) : "l"(v));
}
__device__ __forceinline__ u64 add2(u64 a, u64 b) {
    u64 r; asm("add.rn.f32x2 %0, %1, %2;" : "=l"(r) : "l"(a), "l"(b)); return r;
}
__device__ __forceinline__ u64 fma2(u64 a, u64 b, u64 c) {
    u64 r; asm("fma.rn.f32x2 %0, %1, %2, %3;" : "=l"(r) : "l"(a), "l"(b), "l"(c)); return r;
}

__global__ __launch_bounds__(256, 3)
void sobel_mean_kernel(const float* __restrict__ x, float* __restrict__ out) {
    const int wq   = blockIdx.x;   // column tile: 0..1
    const int hs   = blockIdx.y;   // row strip:   0..63
    const int b    = blockIdx.z;
    const int tid  = threadIdx.x;
    const int wid  = tid >> 5;
    const int lane = tid & 31;

    const int gw4 = wq * TW + lane * 4;  // first of this lane's 4 columns
    const int gh0 = hs * RR;             // first output row of the strip

    const bool top_oob = (hs == 0);
    const bool bot_oob = (hs == HSTRIPS - 1);

    __shared__ float s_acc[NWARPS][RR * TW];   // 16 KB

    const u64 TWO2 = pk(2.0f, 2.0f);
    const u64 NEG1 = pk(-1.0f, -1.0f);
    const u64 EPS2 = pk(1e-12f, 1e-12f);

    float4 acc[RR];
#pragma unroll
    for (int r = 0; r < RR; r++) acc[r] = make_float4(0.f, 0.f, 0.f, 0.f);

    const bool has_left  = (gw4 != 0);
    const bool has_right = (gw4 + 4 != WW);

#pragma unroll 1
    for (int k = 0; k < CC / NWARPS; k++) {
        const float* __restrict__ plane =
            x + ((size_t)(b * CC + wid + NWARPS * k)) * (HH * WW);

        // ---- Phase 1: issue ALL 18 loads for the 6-row strip up front ----
        ulonglong2 vv[NROWS];
        float lf[NROWS], rg[NROWS];
#pragma unroll
        for (int i = 0; i < NROWS; i++) {
            const int gh = gh0 - 1 + i;
            const bool oob = (i == 0 && top_oob) || (i == NROWS - 1 && bot_oob);
            const float* __restrict__ row = plane + gh * WW;
            if (oob) {
                vv[i].x = 0; vv[i].y = 0;
                lf[i] = 0.f; rg[i] = 0.f;
            } else {
                vv[i] = *reinterpret_cast<const ulonglong2*>(row + gw4);
                lf[i] = has_left  ? row[gw4 - 1] : 0.f;
                rg[i] = has_right ? row[gw4 + 4] : 0.f;
            }
        }

        // ---- Phase 2: rolling p/q window over the preloaded rows ----
        u64 p0l = 0, p0h = 0, p1l = 0, p1h = 0;
        u64 q0l = 0, q0h = 0, q1l = 0, q1h = 0;
#pragma unroll
        for (int i = 0; i < NROWS; i++) {
            const u64 cl = vv[i].x;            // (v0, v1)
            const u64 ch = vv[i].y;            // (v2, v3)
            float v0, v1, v2, v3;
            upk(v0, v1, cl);
            upk(v2, v3, ch);
            const u64 ll = pk(lf[i], v0);
            const u64 lh = pk(v1, v2);
            const u64 rh = pk(v3, rg[i]);

            const u64 pl = fma2(NEG1, ll, lh);            // r - l
            const u64 ph = fma2(NEG1, lh, rh);
            const u64 ql = add2(fma2(cl, TWO2, ll), lh);  // l + 2c + r
            const u64 qh = add2(fma2(ch, TWO2, lh), rh);

            if (i >= 2) {
                const int r = i - 2;
                const u64 gxl = add2(fma2(p1l, TWO2, p0l), pl);
                const u64 gxh = add2(fma2(p1h, TWO2, p0h), ph);
                const u64 gyl = fma2(NEG1, q0l, ql);
                const u64 gyh = fma2(NEG1, q0h, qh);
                const u64 m_l = fma2(gxl, gxl, fma2(gyl, gyl, EPS2));
                const u64 m_h = fma2(gxh, gxh, fma2(gyh, gyh, EPS2));
                float m0, m1, m2, m3;
                upk(m0, m1, m_l);
                upk(m2, m3, m_h);
                acc[r].x += sqrt_approx(m0);
                acc[r].y += sqrt_approx(m1);
                acc[r].z += sqrt_approx(m2);
                acc[r].w += sqrt_approx(m3);
            }
            p0l = p1l; p0h = p1h; p1l = pl; p1h = ph;
            q0l = q1l; q0h = q1h; q1l = ql; q1h = qh;
        }
    }

    // Stage per-warp partials, then block-reduce across the 8 warps.
#pragma unroll
    for (int r = 0; r < RR; r++)
        *reinterpret_cast<float4*>(&s_acc[wid][r * TW + lane * 4]) = acc[r];
    __syncthreads();

    const float inv = 1.0f / (float)CC;
#pragma unroll
    for (int j = 0; j < (RR * TW) / 256; j++) {
        const int px = tid + 256 * j;          // 0..511
        float s = 0.f;
#pragma unroll
        for (int w = 0; w < NWARPS; w++) s += s_acc[w][px];
        const int r   = px / TW;
        const int col = px % TW;
        out[((size_t)b * HH + (gh0 + r)) * WW + wq * TW + col] = s * inv;
    }
}

extern "C" void kernel_launch(void* const* d_in, const int* in_sizes, int n_in,
                              void* d_out, int out_size) {
    const float* x = (const float*)d_in[0];
    float* out = (float*)d_out;
    dim3 grid(WW / TW, HSTRIPS, BB);   // (2, 64, 16) = 2048 blocks
    sobel_mean_kernel<<<grid, 256>>>(x, out);
}